// round 1
// baseline (speedup 1.0000x reference)
#include <cuda_runtime.h>
#include <math.h>

#define NN 100000
#define EE 1600000
#define FF 64
#define DEPTH 4

typedef unsigned long long u64;

// ------------------- scratch (device globals; no allocs) -------------------
__device__ float g_P[(size_t)NN * 128];     // per-layer node projections [N,128]
__device__ float g_hbuf[2][(size_t)NN * 64];
__device__ float g_xbuf[2][(size_t)NN * 3];
__device__ float g_hacc[(size_t)NN * 64];
__device__ float g_xacc[(size_t)NN * 3];
__device__ float g_t[(size_t)NN * 64];

// ------------------- helpers -------------------
__device__ __forceinline__ float silu_f(float v) {
    return __fdividef(v, 1.0f + __expf(-v));
}
__device__ __forceinline__ u64 pack2(float v) {
    u64 r; asm("mov.b64 %0, {%1, %1};" : "=l"(r) : "f"(v)); return r;
}
__device__ __forceinline__ void ffma2(u64 &d, u64 a, u64 b) {
    asm("fma.rn.f32x2 %0, %1, %2, %3;" : "=l"(d) : "l"(a), "l"(b), "l"(d));
}
__device__ __forceinline__ void unpack2(u64 v, float &lo, float &hi) {
    asm("mov.b64 {%0, %1}, %2;" : "=f"(lo), "=f"(hi) : "l"(v));
}
__device__ __forceinline__ void red4(float* p, float a, float b, float c, float d) {
    asm volatile("red.global.add.v4.f32 [%0], {%1,%2,%3,%4};"
                 :: "l"(p), "f"(a), "f"(b), "f"(c), "f"(d) : "memory");
}
__device__ __forceinline__ void red1(float* p, float a) {
    asm volatile("red.global.add.f32 [%0], %1;" :: "l"(p), "f"(a) : "memory");
}

// ------------------- zero accumulators -------------------
__global__ void zero_kernel(float* __restrict__ hacc, float* __restrict__ xacc,
                            int nh, int nx) {
    int i = blockIdx.x * blockDim.x + threadIdx.x;
    if (i < nh) hacc[i] = 0.f;
    if (i < nx) xacc[i] = 0.f;
}

// ------------------- P = h @ [Wa | Wb]  (Wa=ew1[0:64], Wb=ew1[64:128]) -------------------
__global__ __launch_bounds__(256) void gemm_P_kernel(
    const float* __restrict__ h, const float* __restrict__ ew1,
    float* __restrict__ P, int n)
{
    extern __shared__ float sm[];
    float* As = sm;              // 64 x 64
    float* Ws = sm + 64 * 64;    // 64 x 128
    int t = threadIdx.x;
    int row0 = blockIdx.x * 64;

    for (int i = t; i < 64 * 64; i += 256) {
        int r = i >> 6, c = i & 63;
        int gr = row0 + r;
        As[i] = (gr < n) ? h[(size_t)gr * 64 + c] : 0.f;
    }
    for (int i = t; i < 64 * 128; i += 256) {
        int k = i >> 7, j = i & 127;
        Ws[i] = (j < 64) ? ew1[k * 64 + j] : ew1[(64 + k) * 64 + (j - 64)];
    }
    __syncthreads();

    int tx = t & 31;       // 32 col groups of 4 -> 128 cols
    int ty = t >> 5;       // 8 row groups of 8
    float acc[8][4];
#pragma unroll
    for (int i = 0; i < 8; i++) { acc[i][0]=0.f; acc[i][1]=0.f; acc[i][2]=0.f; acc[i][3]=0.f; }

    const float4* Wq = (const float4*)Ws;
#pragma unroll 8
    for (int k = 0; k < 64; k++) {
        float4 w = Wq[k * 32 + tx];
#pragma unroll
        for (int i = 0; i < 8; i++) {
            float av = As[(ty * 8 + i) * 64 + k];
            acc[i][0] += av * w.x; acc[i][1] += av * w.y;
            acc[i][2] += av * w.z; acc[i][3] += av * w.w;
        }
    }
#pragma unroll
    for (int i = 0; i < 8; i++) {
        int row = row0 + ty * 8 + i;
        if (row < n) {
            float4 o = make_float4(acc[i][0], acc[i][1], acc[i][2], acc[i][3]);
            ((float4*)P)[(size_t)row * 32 + tx] = o;
        }
    }
}

// ------------------- edge kernel: thread per edge -------------------
__global__ __launch_bounds__(128) void edge_kernel(
    const int* __restrict__ src, const int* __restrict__ dst,
    const float* __restrict__ x, const float* __restrict__ P,
    const float* __restrict__ wr,  const float* __restrict__ eb1,
    const float* __restrict__ ew2, const float* __restrict__ eb2,
    const float* __restrict__ cw1, const float* __restrict__ cb1,
    const float* __restrict__ cw2,
    float* __restrict__ hacc, float* __restrict__ xacc, int E)
{
    __shared__ __align__(16) float s_w2[4096];
    __shared__ __align__(16) float s_c1[4096];
    __shared__ __align__(16) float s_wr[64];
    __shared__ __align__(16) float s_eb1[64];
    __shared__ __align__(16) float s_eb2[64];
    __shared__ __align__(16) float s_cb1[64];
    __shared__ __align__(16) float s_cw2[64];

    int t = threadIdx.x;
    for (int i = t; i < 4096; i += 128) { s_w2[i] = ew2[i]; s_c1[i] = cw1[i]; }
    if (t < 64) {
        s_wr[t] = wr[t]; s_eb1[t] = eb1[t]; s_eb2[t] = eb2[t];
        s_cb1[t] = cb1[t]; s_cw2[t] = cw2[t];
    }
    __syncthreads();

    int e = blockIdx.x * 128 + t;
    if (e >= E) return;

    int si = src[e], di = dst[e];

    float dx0 = x[si * 3 + 0] - x[di * 3 + 0];
    float dx1 = x[si * 3 + 1] - x[di * 3 + 1];
    float dx2 = x[si * 3 + 2] - x[di * 3 + 2];
    float r = dx0 * dx0 + dx1 * dx1 + dx2 * dx2;
    float inv = __fdividef(1.0f, sqrtf(r) + 1e-30f);
    float u0 = dx0 * inv, u1 = dx1 * inv, u2 = dx2 * inv;

    // m1 = silu(P[src][0:64] + P[dst][64:128] + r*wr + eb1)
    float a[64];
    {
        const float4* Pa = (const float4*)(P + (size_t)si * 128);
        const float4* Pb = (const float4*)(P + (size_t)di * 128 + 64);
#pragma unroll
        for (int i = 0; i < 16; i++) {
            float4 va = Pa[i], vb = Pb[i];
            a[4*i+0] = silu_f(va.x + vb.x + r * s_wr[4*i+0] + s_eb1[4*i+0]);
            a[4*i+1] = silu_f(va.y + vb.y + r * s_wr[4*i+1] + s_eb1[4*i+1]);
            a[4*i+2] = silu_f(va.z + vb.z + r * s_wr[4*i+2] + s_eb1[4*i+2]);
            a[4*i+3] = silu_f(va.w + vb.w + r * s_wr[4*i+3] + s_eb1[4*i+3]);
        }
    }

    u64 acc[32];

    // ---- GEMM1: m = silu(m1 @ ew2 + eb2) ----
    {
        const u64* bq = (const u64*)s_eb2;
#pragma unroll
        for (int j = 0; j < 32; j++) acc[j] = bq[j];
        const ulonglong2* wq = (const ulonglong2*)s_w2;
#pragma unroll
        for (int k = 0; k < 64; k++) {
            u64 ak = pack2(a[k]);
#pragma unroll
            for (int j = 0; j < 16; j++) {
                ulonglong2 w = wq[k * 16 + j];
                ffma2(acc[2*j+0], ak, w.x);
                ffma2(acc[2*j+1], ak, w.y);
            }
        }
#pragma unroll
        for (int j = 0; j < 32; j++) {
            float lo, hi; unpack2(acc[j], lo, hi);
            a[2*j+0] = silu_f(lo);
            a[2*j+1] = silu_f(hi);
        }
    }

    // scatter m into h_acc[dst]
    {
        float* hp = hacc + (size_t)di * 64;
#pragma unroll
        for (int i = 0; i < 16; i++)
            red4(hp + 4*i, a[4*i+0], a[4*i+1], a[4*i+2], a[4*i+3]);
    }

    // ---- GEMM2: c1 = silu(m @ cw1 + cb1); c = c1 . cw2 ----
    float c;
    {
        const u64* bq = (const u64*)s_cb1;
#pragma unroll
        for (int j = 0; j < 32; j++) acc[j] = bq[j];
        const ulonglong2* wq = (const ulonglong2*)s_c1;
#pragma unroll
        for (int k = 0; k < 64; k++) {
            u64 ak = pack2(a[k]);
#pragma unroll
            for (int j = 0; j < 16; j++) {
                ulonglong2 w = wq[k * 16 + j];
                ffma2(acc[2*j+0], ak, w.x);
                ffma2(acc[2*j+1], ak, w.y);
            }
        }
        c = 0.f;
#pragma unroll
        for (int j = 0; j < 32; j++) {
            float lo, hi; unpack2(acc[j], lo, hi);
            c += silu_f(lo) * s_cw2[2*j+0];
            c += silu_f(hi) * s_cw2[2*j+1];
        }
    }

    // scatter msg_x into x_acc[dst]
    float* xp = xacc + (size_t)di * 3;
    red1(xp + 0, c * u0);
    red1(xp + 1, c * u1);
    red1(xp + 2, c * u2);
}

// ------------------- node GEMM: out = act(A @ W + b), A = [A1 | A2] -------------------
template<int K, bool ACT>
__global__ __launch_bounds__(256) void node_gemm_kernel(
    const float* __restrict__ A1, const float* __restrict__ A2,
    const float* __restrict__ W, const float* __restrict__ bias,
    float* __restrict__ out, int n)
{
    extern __shared__ float sm[];
    float* As = sm;            // 64 x K
    float* Ws = sm + 64 * K;   // K x 64
    int t = threadIdx.x;
    int row0 = blockIdx.x * 64;

    for (int i = t; i < 64 * K; i += 256) {
        int r = i / K, c = i % K;
        int gr = row0 + r;
        float v = 0.f;
        if (gr < n) {
            if (K == 64 || c < 64) v = A1[(size_t)gr * 64 + (c & 63)];
            else                   v = A2[(size_t)gr * 64 + (c - 64)];
        }
        As[i] = v;
    }
    for (int i = t; i < K * 64; i += 256) Ws[i] = W[i];
    __syncthreads();

    int tx = t & 15;     // 16 col groups of 4 -> 64 cols
    int ty = t >> 4;     // 16 row groups of 4
    float acc[4][4];
#pragma unroll
    for (int i = 0; i < 4; i++) { acc[i][0]=0.f; acc[i][1]=0.f; acc[i][2]=0.f; acc[i][3]=0.f; }

    const float4* Wq = (const float4*)Ws;
#pragma unroll 8
    for (int k = 0; k < K; k++) {
        float4 w = Wq[k * 16 + tx];
#pragma unroll
        for (int i = 0; i < 4; i++) {
            float av = As[(ty * 4 + i) * K + k];
            acc[i][0] += av * w.x; acc[i][1] += av * w.y;
            acc[i][2] += av * w.z; acc[i][3] += av * w.w;
        }
    }

    float b0 = bias[tx*4+0], b1 = bias[tx*4+1], b2 = bias[tx*4+2], b3 = bias[tx*4+3];
#pragma unroll
    for (int i = 0; i < 4; i++) {
        int row = row0 + ty * 4 + i;
        if (row < n) {
            float4 o;
            o.x = acc[i][0] + b0; o.y = acc[i][1] + b1;
            o.z = acc[i][2] + b2; o.w = acc[i][3] + b3;
            if (ACT) { o.x = silu_f(o.x); o.y = silu_f(o.y); o.z = silu_f(o.z); o.w = silu_f(o.w); }
            ((float4*)out)[(size_t)row * 16 + tx] = o;
        }
    }
}

// ------------------- x update -------------------
__global__ void xupd_kernel(const float* __restrict__ x, const float* __restrict__ xacc,
                            float* __restrict__ out, int n3)
{
    int i = blockIdx.x * blockDim.x + threadIdx.x;
    if (i < n3) out[i] = x[i] + xacc[i];
}

// ------------------- launch -------------------
extern "C" void kernel_launch(void* const* d_in, const int* in_sizes, int n_in,
                              void* d_out, int out_size)
{
    const float* h0  = (const float*)d_in[0];
    const float* x0  = (const float*)d_in[1];
    const int*   src = (const int*)d_in[2];
    const int*   dst = (const int*)d_in[3];
    const float* ew1 = (const float*)d_in[4];
    const float* eb1 = (const float*)d_in[5];
    const float* ew2 = (const float*)d_in[6];
    const float* eb2 = (const float*)d_in[7];
    const float* nw1 = (const float*)d_in[8];
    const float* nb1 = (const float*)d_in[9];
    const float* nw2 = (const float*)d_in[10];
    const float* nb2 = (const float*)d_in[11];
    const float* cw1 = (const float*)d_in[12];
    const float* cb1 = (const float*)d_in[13];
    const float* cw2 = (const float*)d_in[14];

    int n = in_sizes[0] / 64;
    int E = in_sizes[2];

    float *P, *hA, *xA, *hacc, *xacc, *tb;
    cudaGetSymbolAddress((void**)&P,    g_P);
    cudaGetSymbolAddress((void**)&hA,   g_hbuf);
    cudaGetSymbolAddress((void**)&xA,   g_xbuf);
    cudaGetSymbolAddress((void**)&hacc, g_hacc);
    cudaGetSymbolAddress((void**)&xacc, g_xacc);
    cudaGetSymbolAddress((void**)&tb,   g_t);

    float* hb[2] = { hA, hA + (size_t)NN * 64 };
    float* xb[2] = { xA, xA + (size_t)NN * 3 };

    const int smP  = (64*64 + 64*128) * 4;
    const int smN1 = (64*128 + 128*64) * 4;
    const int smN2 = (64*64 + 64*64) * 4;
    cudaFuncSetAttribute(gemm_P_kernel, cudaFuncAttributeMaxDynamicSharedMemorySize, smP);
    cudaFuncSetAttribute(node_gemm_kernel<128, true>,  cudaFuncAttributeMaxDynamicSharedMemorySize, smN1);
    cudaFuncSetAttribute(node_gemm_kernel<64, false>,  cudaFuncAttributeMaxDynamicSharedMemorySize, smN2);

    int nb_rows = (n + 63) / 64;
    int eb_blocks = (E + 127) / 128;

    for (int d = 0; d < DEPTH; d++) {
        const float* hc = d ? hb[(d - 1) & 1] : h0;
        const float* xc = d ? xb[(d - 1) & 1] : x0;
        float* xo = (d == DEPTH - 1) ? (float*)d_out : xb[d & 1];

        zero_kernel<<<(n * 64 + 255) / 256, 256>>>(hacc, xacc, n * 64, n * 3);

        gemm_P_kernel<<<nb_rows, 256, smP>>>(hc, ew1 + (size_t)d * 129 * 64, P, n);

        edge_kernel<<<eb_blocks, 128>>>(
            src, dst, xc, P,
            ew1 + (size_t)d * 129 * 64 + 128 * 64, eb1 + d * 64,
            ew2 + (size_t)d * 4096, eb2 + d * 64,
            cw1 + (size_t)d * 4096, cb1 + d * 64, cw2 + d * 64,
            hacc, xacc, E);

        if (d < DEPTH - 1) {
            node_gemm_kernel<128, true><<<nb_rows, 256, smN1>>>(
                hc, hacc, nw1 + (size_t)d * 128 * 64, nb1 + d * 64, tb, n);
            node_gemm_kernel<64, false><<<nb_rows, 256, smN2>>>(
                tb, tb, nw2 + (size_t)d * 4096, nb2 + d * 64, hb[d & 1], n);
        }

        xupd_kernel<<<(n * 3 + 255) / 256, 256>>>(xc, xacc, xo, n * 3);
    }
}